// round 16
// baseline (speedup 1.0000x reference)
#include <cuda_runtime.h>
#include <cuda_fp16.h>
#include <cstdint>

// Problem constants (match reference_code)
#define N0c 200000
#define N1c 50000
#define N2c 12500
#define N3c 3200
#define E0c 500000
#define E1c 125000
#define E2c 32000
#define DINc 128
#define DHc 256
#define DOUTc 128

// ---------------- scratch (static device globals; no allocations) ----------------
__device__ __half g_x16[(size_t)N0c * DINc];     // fp16 copy of x (51.2 MB)
__device__ __half g_w16[262144];                 // fp16 weights, concatenated
// offsets (halves): wl0@0, wr0@32768, wl1@65536, wr1@131072, wl2@196608, wr2@229376
#define W16_WL0 0
#define W16_WR0 32768
#define W16_WL1 65536
#define W16_WR1 131072
#define W16_WL2 196608
#define W16_WR2 229376
__device__ __half g_mean[(size_t)N1c * DHc];
__device__ __half g_h1[(size_t)N1c * DHc];
__device__ __half g_h2[(size_t)N2c * DHc];
__device__ int g_deg0[N1c]; __device__ int g_off0[N1c + 1]; __device__ int g_cur0[N1c]; __device__ int g_esrc0[E0c];
__device__ int g_deg1[N2c]; __device__ int g_off1[N2c + 1]; __device__ int g_cur1[N2c]; __device__ int g_esrc1[E1c];
__device__ int g_deg2[N3c]; __device__ int g_off2[N3c + 1]; __device__ int g_cur2[N3c]; __device__ int g_esrc2[E2c];

// ---------------- one-shot fp32 -> fp16 conversion (x + weights) ----------------
__device__ __forceinline__ uint2 f4toh4(float4 v) {
    __half2 p0 = __floats2half2_rn(v.x, v.y);
    __half2 p1 = __floats2half2_rn(v.z, v.w);
    return make_uint2(*(uint32_t*)&p0, *(uint32_t*)&p1);
}

__global__ void cvt_kernel(const float* __restrict__ x,
                           const float* __restrict__ wl0, const float* __restrict__ wr0,
                           const float* __restrict__ wl1, const float* __restrict__ wr1,
                           const float* __restrict__ wl2, const float* __restrict__ wr2) {
    int tid = blockIdx.x * blockDim.x + threadIdx.x;
    int stride = gridDim.x * blockDim.x;
    const int NX4 = (N0c * DINc) / 4;       // 6.4M float4
    uint2* x16 = (uint2*)g_x16;
    for (int i = tid; i < NX4; i += stride)
        x16[i] = f4toh4(((const float4*)x)[i]);

    // weights: 65536 float4 total
    const int S0 = (DHc * DINc) / 4;   // 8192
    const int S1 = (DHc * DHc) / 4;    // 16384
    const int S2 = (DOUTc * DHc) / 4;  // 8192
    uint2* w16 = (uint2*)g_w16;
    for (int i = tid; i < 2 * S0 + 2 * S1 + 2 * S2; i += stride) {
        float4 v;
        int o = i;
        if (o < S0)                { v = ((const float4*)wl0)[o]; }
        else if ((o -= S0) < S0)   { v = ((const float4*)wr0)[o]; }
        else if ((o -= S0) < S1)   { v = ((const float4*)wl1)[o]; }
        else if ((o -= S1) < S1)   { v = ((const float4*)wr1)[o]; }
        else if ((o -= S1) < S2)   { v = ((const float4*)wl2)[o]; }
        else { o -= S2;              v = ((const float4*)wr2)[o]; }
        w16[i] = f4toh4(v);
    }
}

// ---------------- batched CSR build (scan re-zeros deg; zero-init covers 1st call) ----------------
__global__ void hist3_kernel(const int* __restrict__ d0, const int* __restrict__ d1,
                             const int* __restrict__ d2) {
    int e = blockIdx.x * blockDim.x + threadIdx.x;
    if (e < E0c) atomicAdd(&g_deg0[d0[e]], 1);
    else if (e < E0c + E1c) atomicAdd(&g_deg1[d1[e - E0c]], 1);
    else if (e < E0c + E1c + E2c) atomicAdd(&g_deg2[d2[e - E0c - E1c]], 1);
}

__global__ void scan3_kernel() {
    const int T = 1024;
    __shared__ int wsum[32];
    int layer = blockIdx.x;
    int n = (layer == 0) ? N1c : (layer == 1) ? N2c : N3c;
    int E = (layer == 0) ? E0c : (layer == 1) ? E1c : E2c;
    int* deg = (layer == 0) ? g_deg0 : (layer == 1) ? g_deg1 : g_deg2;
    int* off = (layer == 0) ? g_off0 : (layer == 1) ? g_off1 : g_off2;
    int* cur = (layer == 0) ? g_cur0 : (layer == 1) ? g_cur1 : g_cur2;

    int tid = threadIdx.x, lane = tid & 31, wid = tid >> 5;
    int chunk = (n + T - 1) / T;
    int beg = min(tid * chunk, n), end = min(beg + chunk, n);

    int sum = 0;
    for (int i = beg; i < end; i++) sum += deg[i];

    int s = sum;
    #pragma unroll
    for (int o = 1; o < 32; o <<= 1) {
        int t = __shfl_up_sync(0xffffffffu, s, o);
        if (lane >= o) s += t;
    }
    if (lane == 31) wsum[wid] = s;
    __syncthreads();
    if (wid == 0) {
        int ws = wsum[lane];
        #pragma unroll
        for (int o = 1; o < 32; o <<= 1) {
            int t = __shfl_up_sync(0xffffffffu, ws, o);
            if (lane >= o) ws += t;
        }
        wsum[lane] = ws;
    }
    __syncthreads();
    int excl = s - sum + ((wid > 0) ? wsum[wid - 1] : 0);

    int run = excl;
    for (int i = beg; i < end; i++) {
        int d = deg[i];
        off[i] = run;
        cur[i] = run;
        run += d;
        deg[i] = 0;
    }
    if (tid == 0) off[n] = E;
}

__global__ void bucket3_kernel(const int* __restrict__ s0, const int* __restrict__ d0,
                               const int* __restrict__ s1, const int* __restrict__ d1,
                               const int* __restrict__ s2, const int* __restrict__ d2) {
    int e = blockIdx.x * blockDim.x + threadIdx.x;
    if (e < E0c) {
        int p = atomicAdd(&g_cur0[d0[e]], 1);
        g_esrc0[p] = s0[e];
    } else if (e < E0c + E1c) {
        int i = e - E0c;
        int p = atomicAdd(&g_cur1[d1[i]], 1);
        g_esrc1[p] = s1[i];
    } else if (e < E0c + E1c + E2c) {
        int i = e - E0c - E1c;
        int p = atomicAdd(&g_cur2[d2[i]], 1);
        g_esrc2[p] = s2[i];
    }
}

// ---------------- aggregation (fp16 in -> fp16 mean), warp per node ----------------
template <int D>
__global__ void aggregate_f16(const __half* __restrict__ X, __half* __restrict__ mean,
                              const int* __restrict__ off, const int* __restrict__ esrc,
                              int n_tgt) {
    int w = (blockIdx.x * blockDim.x + threadIdx.x) >> 5;
    int lane = threadIdx.x & 31;
    if (w >= n_tgt) return;
    int beg = off[w], end = off[w + 1];
    float acc[D / 32];
    #pragma unroll
    for (int i = 0; i < D / 32; i++) acc[i] = 0.f;
    int e = beg;
    for (; e + 1 < end; e += 2) {
        int s0 = esrc[e], s1 = esrc[e + 1];
        const uint2* r0 = (const uint2*)(X + (size_t)s0 * D);
        const uint2* r1 = (const uint2*)(X + (size_t)s1 * D);
        #pragma unroll
        for (int i = 0; i < D / 128; i++) {
            uint2 u0 = r0[lane + 32 * i];
            uint2 u1 = r1[lane + 32 * i];
            float2 a0 = __half22float2(*(__half2*)&u0.x);
            float2 a1 = __half22float2(*(__half2*)&u0.y);
            float2 b0 = __half22float2(*(__half2*)&u1.x);
            float2 b1 = __half22float2(*(__half2*)&u1.y);
            acc[4 * i + 0] += a0.x + b0.x;
            acc[4 * i + 1] += a0.y + b0.y;
            acc[4 * i + 2] += a1.x + b1.x;
            acc[4 * i + 3] += a1.y + b1.y;
        }
    }
    if (e < end) {
        const uint2* r0 = (const uint2*)(X + (size_t)esrc[e] * D);
        #pragma unroll
        for (int i = 0; i < D / 128; i++) {
            uint2 u0 = r0[lane + 32 * i];
            float2 a0 = __half22float2(*(__half2*)&u0.x);
            float2 a1 = __half22float2(*(__half2*)&u0.y);
            acc[4 * i + 0] += a0.x;
            acc[4 * i + 1] += a0.y;
            acc[4 * i + 2] += a1.x;
            acc[4 * i + 3] += a1.y;
        }
    }
    float inv = 1.f / (float)max(end - beg, 1);
    uint2* mrow = (uint2*)(mean + (size_t)w * D);
    #pragma unroll
    for (int i = 0; i < D / 128; i++) {
        __half2 p0 = __floats2half2_rn(acc[4 * i + 0] * inv, acc[4 * i + 1] * inv);
        __half2 p1 = __floats2half2_rn(acc[4 * i + 2] * inv, acc[4 * i + 3] * inv);
        mrow[lane + 32 * i] = make_uint2(*(uint32_t*)&p0, *(uint32_t*)&p1);
    }
}

// ---------------- all-fp16 + ldmatrix fused dual-A GEMM ----------------
// out = act( mean@Wl^T + x_tgt@Wr^T + b ). Block 128x128, BK=32, 8 warps (2m x 4n),
// warp tile 64x32 = 4x4 m16n8k16, fp32 accum. A0, A1, Wl, Wr all fp16.

#define LDK 40   // halves per row (32 data + 8 pad); row stride 80 B

__device__ __forceinline__ uint32_t smem_u32(const void* p) {
    return (uint32_t)__cvta_generic_to_shared(p);
}

template <bool OUTH>
__global__ void __launch_bounds__(256) sage_gemm(
    const __half* __restrict__ A0, const __half* __restrict__ A1,
    const __half* __restrict__ Wl, const __half* __restrict__ Wr,
    const float* __restrict__ bias, void* __restrict__ outv,
    int M, int N, int D, int relu)
{
    __shared__ __half As[128 * LDK];
    __shared__ __half Bs[128 * LDK];

    int tid = threadIdx.x;
    int lane = tid & 31, wid = tid >> 5;
    int wm = wid & 1;
    int wn = wid >> 1;
    int g = lane >> 2, t = lane & 3;

    int rowBase = blockIdx.x * 128, colBase = blockIdx.y * 128;

    float acc[4][4][4];
    #pragma unroll
    for (int i = 0; i < 4; i++)
        #pragma unroll
        for (int j = 0; j < 4; j++)
            #pragma unroll
            for (int r = 0; r < 4; r++) acc[i][j][r] = 0.f;

    int ldr = tid >> 3;
    int ldc = (tid & 7) * 4;

    int lrowA = lane & 15;
    int lkA   = (lane >> 4) << 3;
    int lrowB = lane & 7;
    int lkB   = ((lane >> 3) & 1) << 3;

    const int NT = (2 * D) / 32;

    for (int it = 0; it < NT; it++) {
        int kt = it * 32;
        bool first = (kt < D);
        const __half* Aop = first ? A0 : A1;
        const __half* W = first ? Wl : Wr;
        int kk = first ? kt : (kt - D);

        #pragma unroll
        for (int s = 0; s < 4; s++) {
            int r = ldr + s * 32;
            int grow = rowBase + r;
            uint2 ua = (grow < M)
                ? *(const uint2*)(Aop + (size_t)grow * D + kk + ldc)
                : make_uint2(0u, 0u);
            *(uint2*)&As[r * LDK + ldc] = ua;
            *(uint2*)&Bs[r * LDK + ldc] =
                *(const uint2*)(W + (size_t)(colBase + r) * D + kk + ldc);
        }
        __syncthreads();

        #pragma unroll
        for (int ks = 0; ks < 32; ks += 16) {
            uint32_t af[4][4];
            #pragma unroll
            for (int mi = 0; mi < 4; mi++) {
                int m = wm * 64 + mi * 16;
                uint32_t addr = smem_u32(&As[(m + lrowA) * LDK + ks + lkA]);
                asm volatile(
                    "ldmatrix.sync.aligned.m8n8.x4.shared.b16 {%0,%1,%2,%3}, [%4];"
                    : "=r"(af[mi][0]), "=r"(af[mi][1]), "=r"(af[mi][2]), "=r"(af[mi][3])
                    : "r"(addr));
            }
            uint32_t bf[4][2];
            #pragma unroll
            for (int ni = 0; ni < 4; ni++) {
                int n = wn * 32 + ni * 8;
                uint32_t addr = smem_u32(&Bs[(n + lrowB) * LDK + ks + lkB]);
                asm volatile(
                    "ldmatrix.sync.aligned.m8n8.x2.shared.b16 {%0,%1}, [%2];"
                    : "=r"(bf[ni][0]), "=r"(bf[ni][1])
                    : "r"(addr));
            }
            #pragma unroll
            for (int mi = 0; mi < 4; mi++)
                #pragma unroll
                for (int ni = 0; ni < 4; ni++) {
                    asm volatile(
                        "mma.sync.aligned.m16n8k16.row.col.f32.f16.f16.f32 "
                        "{%0,%1,%2,%3}, {%4,%5,%6,%7}, {%8,%9}, {%0,%1,%2,%3};"
                        : "+f"(acc[mi][ni][0]), "+f"(acc[mi][ni][1]),
                          "+f"(acc[mi][ni][2]), "+f"(acc[mi][ni][3])
                        : "r"(af[mi][0]), "r"(af[mi][1]), "r"(af[mi][2]), "r"(af[mi][3]),
                          "r"(bf[ni][0]), "r"(bf[ni][1]));
                }
        }
        __syncthreads();
    }

    #pragma unroll
    for (int mi = 0; mi < 4; mi++) {
        #pragma unroll
        for (int ni = 0; ni < 4; ni++) {
            int col = colBase + wn * 32 + ni * 8 + t * 2;
            float b0v = bias[col], b1v = bias[col + 1];
            #pragma unroll
            for (int h = 0; h < 2; h++) {
                int row = rowBase + wm * 64 + mi * 16 + g + 8 * h;
                if (row >= M) continue;
                float ox = acc[mi][ni][2 * h + 0] + b0v;
                float oy = acc[mi][ni][2 * h + 1] + b1v;
                if (relu) { ox = fmaxf(ox, 0.f); oy = fmaxf(oy, 0.f); }
                if (OUTH) {
                    __half2 p = __floats2half2_rn(ox, oy);
                    *(uint32_t*)((__half*)outv + (size_t)row * N + col) = *(uint32_t*)&p;
                } else {
                    *(float2*)((float*)outv + (size_t)row * N + col) = make_float2(ox, oy);
                }
            }
        }
    }
}

extern "C" void kernel_launch(void* const* d_in, const int* in_sizes, int n_in,
                              void* d_out, int out_size)
{
    const float* x    = (const float*)d_in[0];
    const int*   src0 = (const int*)d_in[1];
    const int*   dst0 = (const int*)d_in[2];
    const int*   src1 = (const int*)d_in[3];
    const int*   dst1 = (const int*)d_in[4];
    const int*   src2 = (const int*)d_in[5];
    const int*   dst2 = (const int*)d_in[6];
    const float* wl0  = (const float*)d_in[7];
    const float* wr0  = (const float*)d_in[8];
    const float* b0   = (const float*)d_in[9];
    const float* wl1  = (const float*)d_in[10];
    const float* wr1  = (const float*)d_in[11];
    const float* b1   = (const float*)d_in[12];
    const float* wl2  = (const float*)d_in[13];
    const float* wr2  = (const float*)d_in[14];
    const float* b2   = (const float*)d_in[15];
    float* out = (float*)d_out;

    static cudaStream_t sC = nullptr;
    static cudaEvent_t evRoot, evCvt;
    if (!sC) {
        cudaStreamCreateWithFlags(&sC, cudaStreamNonBlocking);
        cudaEventCreateWithFlags(&evRoot, cudaEventDisableTiming);
        cudaEventCreateWithFlags(&evCvt, cudaEventDisableTiming);
    }

    __half *h1, *h2, *mean, *x16, *w16;
    cudaGetSymbolAddress((void**)&h1, g_h1);
    cudaGetSymbolAddress((void**)&h2, g_h2);
    cudaGetSymbolAddress((void**)&mean, g_mean);
    cudaGetSymbolAddress((void**)&x16, g_x16);
    cudaGetSymbolAddress((void**)&w16, g_w16);
    int *off0, *off1, *off2, *es0, *es1, *es2;
    cudaGetSymbolAddress((void**)&off0, g_off0);
    cudaGetSymbolAddress((void**)&off1, g_off1);
    cudaGetSymbolAddress((void**)&off2, g_off2);
    cudaGetSymbolAddress((void**)&es0, g_esrc0);
    cudaGetSymbolAddress((void**)&es1, g_esrc1);
    cudaGetSymbolAddress((void**)&es2, g_esrc2);

    // ---- fork: fp16 conversion of x + weights overlapping the CSR chain ----
    cudaEventRecord(evRoot, 0);
    cudaStreamWaitEvent(sC, evRoot, 0);
    cvt_kernel<<<2048, 256, 0, sC>>>(x, wl0, wr0, wl1, wr1, wl2, wr2);
    cudaEventRecord(evCvt, sC);

    // ---- main stream: batched CSR ----
    const int ETOT = E0c + E1c + E2c;
    hist3_kernel<<<(ETOT + 255) / 256, 256>>>(dst0, dst1, dst2);
    scan3_kernel<<<3, 1024>>>();
    bucket3_kernel<<<(ETOT + 255) / 256, 256>>>(src0, dst0, src1, dst1, src2, dst2);
    cudaStreamWaitEvent(0, evCvt, 0);

    // Layer 0: x16 (fp16) -> h1 (fp16), relu
    aggregate_f16<128><<<(N1c * 32 + 255) / 256, 256>>>(x16, mean, off0, es0, N1c);
    dim3 g0((N1c + 127) / 128, 2);
    sage_gemm<true><<<g0, 256>>>(mean, x16, w16 + W16_WL0, w16 + W16_WR0,
                                 b0, h1, N1c, DHc, DINc, 1);

    // Layer 1: h1 (fp16) -> h2 (fp16), relu
    aggregate_f16<256><<<(N2c * 32 + 255) / 256, 256>>>(h1, mean, off1, es1, N2c);
    dim3 g1((N2c + 127) / 128, 2);
    sage_gemm<true><<<g1, 256>>>(mean, h1, w16 + W16_WL1, w16 + W16_WR1,
                                 b1, h2, N2c, DHc, DHc, 1);

    // Layer 2: h2 (fp16) -> out (fp32), no relu
    aggregate_f16<256><<<(N3c * 32 + 255) / 256, 256>>>(h2, mean, off2, es2, N3c);
    dim3 g2((N3c + 127) / 128, 1);
    sage_gemm<false><<<g2, 256>>>(mean, h2, w16 + W16_WL2, w16 + W16_WR2,
                                  b2, out, N3c, DOUTc, DHc, 0);
}